// round 17
// baseline (speedup 1.0000x reference)
#include <cuda_runtime.h>
#include <cuda_fp16.h>
#include <cstdint>
#include <cstring>

#define CIN 512
#define SEQ 1024

// ---------------- scratch ----------------
__device__ __half  g_inp16[2 * 512 * 1024];            // [b][c][s]
__device__ __half  g_W16[3 * 512 * 1024];              // [w][c][h*64+d] scale-folded
__device__ __half  g_Wo16[1024 * 512];                 // [j'=v*64+d][c]
__device__ __half  g_Qh[2 * 16 * 1024 * 64];           // [b][h][s][d]
__device__ __half  g_Kh[2 * 16 * 1024 * 64];           // [b][h][s][d]
__device__ __half  g_Vh[2 * 16 * 1024 * 64];           // [b][h][k][d]
__device__ uint8_t g_J[(size_t)2 * 16 * 1024 * 1024];  // [b][h][q][k] e4m3, 32 MB
__device__ uint8_t g_U[(size_t)2 * 16 * 1024 * 1024];  // [b][v][q][k] e4m3 (x65536), 32 MB
__device__ __half  g_Oh[2 * 1024 * 1024];              // [b][q][v*64+d] fp16

#define USCALE 65536.0f
#define UINV   (1.0f / 65536.0f)

// ---------------- exp via MUFU ----------------
__device__ __forceinline__ float fast_exp(float x) {
    float r;
    asm("ex2.approx.f32 %0, %1;" : "=f"(r) : "f"(x * 1.4426950408889634f));
    return r;
}

// bit-cast half2 -> uint32
__device__ __forceinline__ uint32_t h2u(__half2 h) {
    uint32_t u;
    memcpy(&u, &h, 4);
    return u;
}

// ---------------- fp8 converts (HW cvt, sm_89+) ----------------
__device__ __forceinline__ uint16_t h2_to_e4m3x2(uint32_t h2) {
    uint16_t r;
    asm("cvt.rn.satfinite.e4m3x2.f16x2 %0, %1;" : "=h"(r) : "r"(h2));
    return r;
}
__device__ __forceinline__ uint32_t e4m3x2_to_h2(uint16_t u) {
    uint32_t r;
    asm("cvt.rn.f16x2.e4m3x2 %0, %1;" : "=r"(r) : "h"(u));
    return r;
}
__device__ __forceinline__ void f8x16_to_h16(uint4 raw, uint4* o) {
    uint16_t* pr = (uint16_t*)&raw;
    uint32_t hh[8];
#pragma unroll
    for (int e = 0; e < 8; e++) hh[e] = e4m3x2_to_h2(pr[e]);
    o[0] = *(uint4*)&hh[0];
    o[1] = *(uint4*)&hh[4];
}
__device__ __forceinline__ uint4 h16_to_f8x16(const uint32_t* hsrc) {
    uint16_t e[8];
#pragma unroll
    for (int p = 0; p < 8; p++) e[p] = h2_to_e4m3x2(hsrc[p]);
    return *(uint4*)e;
}

// ---------------- mma helpers ----------------
__device__ __forceinline__ uint32_t cvta_s(const void* p) {
    return (uint32_t)__cvta_generic_to_shared(p);
}
__device__ __forceinline__ void ldm4(uint32_t* r, uint32_t a) {
    asm volatile("ldmatrix.sync.aligned.m8n8.x4.shared.b16 {%0,%1,%2,%3}, [%4];"
        : "=r"(r[0]), "=r"(r[1]), "=r"(r[2]), "=r"(r[3]) : "r"(a));
}
__device__ __forceinline__ void ldm4t(uint32_t* r, uint32_t a) {
    asm volatile("ldmatrix.sync.aligned.m8n8.x4.trans.shared.b16 {%0,%1,%2,%3}, [%4];"
        : "=r"(r[0]), "=r"(r[1]), "=r"(r[2]), "=r"(r[3]) : "r"(a));
}
__device__ __forceinline__ void mma16816(float* c, const uint32_t* a, const uint32_t* b) {
    asm volatile("mma.sync.aligned.m16n8k16.row.col.f32.f16.f16.f32 "
        "{%0,%1,%2,%3}, {%4,%5,%6,%7}, {%8,%9}, {%0,%1,%2,%3};"
        : "+f"(c[0]), "+f"(c[1]), "+f"(c[2]), "+f"(c[3])
        : "r"(a[0]), "r"(a[1]), "r"(a[2]), "r"(a[3]), "r"(b[0]), "r"(b[1]));
}

// ================= KC0: fp16 conversions + weight reorders =================
__global__ __launch_bounds__(256) void kc0(const float* __restrict__ inp,
        const float* __restrict__ Wq, const float* __restrict__ Wk,
        const float* __restrict__ Wv,
        const float* __restrict__ aq, const float* __restrict__ ak,
        const float* __restrict__ av, const float* __restrict__ Wo) {
    int bid = blockIdx.x, tid = threadIdx.x;
    if (bid < 2048) {
        int t = bid * 256 + tid;
        float2 v = *(const float2*)(inp + (size_t)t * 2);
        *(__half2*)(g_inp16 + (size_t)t * 2) = __floats2half2_rn(v.x, v.y);
        return;
    }
    if (bid < 2240) {
        __shared__ __half sT[8 * 1024];
        int u = bid - 2048;
        int w = u >> 6, r0 = (u & 63) * 8;
        const float* W = (w == 0) ? Wq : ((w == 1) ? Wk : Wv);
        float al = (w == 0) ? aq[0] : ((w == 1) ? ak[0] : av[0]);
        float sc = 1.0f / (1.0f + fast_exp(-al));
#pragma unroll
        for (int i = 0; i < 8; i++) {
            int idx = i * 256 + tid;
            int row = idx >> 8, col4 = (idx & 255) * 4;
            float4 v = *(const float4*)&W[(r0 + row) * 1024 + col4];
            __half* d = &sT[row * 1024 + col4];
            d[0] = __float2half_rn(v.x * sc);
            d[1] = __float2half_rn(v.y * sc);
            d[2] = __float2half_rn(v.z * sc);
            d[3] = __float2half_rn(v.w * sc);
        }
        __syncthreads();
#pragma unroll
        for (int i = 0; i < 4; i++) {
            int idx = i * 256 + tid;
            int row = idx >> 7, jo8 = (idx & 127) * 8;
            __half outv[8];
#pragma unroll
            for (int e = 0; e < 8; e++) {
                int jp = jo8 + e;
                outv[e] = sT[row * 1024 + (jp & 63) * 16 + (jp >> 6)];
            }
            *(uint4*)&g_W16[w * 524288 + (r0 + row) * 1024 + jo8] = *(uint4*)outv;
        }
        return;
    }
    {
        int u2 = (bid - 2240) * 256 + tid;
        int jp = u2 >> 8, cp = (u2 & 255) * 2;
        int wrow = ((jp & 63) << 4) | (jp >> 6);
        *(__half2*)(g_Wo16 + jp * 512 + cp) =
            __floats2half2_rn(Wo[wrow * 512 + cp], Wo[wrow * 512 + cp + 1]);
    }
}

// ================= K1: QKV projection, HMMA, 128x128, KC=32 DB, staged epilogue ====
__global__ __launch_bounds__(256) void k1_proj() {
    __shared__ __half s1[17408];
    __half* Asb[2] = { s1, s1 + 4352 };
    __half* Bsb[2] = { s1 + 8704, s1 + 13056 };
    int z = blockIdx.z;
    int b = z / 3, w = z % 3;
    int n0 = blockIdx.x * 128, m0 = blockIdx.y * 128;
    const __half* Ag = g_inp16 + b * 524288;
    const __half* Bg = g_W16 + w * 524288;

    int t = threadIdx.x, lane = t & 31, warp = t >> 5;
    int lrow = t >> 3, lcol = (t & 7) * 16;

    {
        const uint4* as = (const uint4*)(Ag + lrow * 1024 + m0 + lcol);
        const uint4* bs = (const uint4*)(Bg + lrow * 1024 + n0 + lcol);
        uint4* ad = (uint4*)(Asb[0] + lrow * 136 + lcol);
        uint4* bd = (uint4*)(Bsb[0] + lrow * 136 + lcol);
        ad[0] = as[0]; ad[1] = as[1];
        bd[0] = bs[0]; bd[1] = bs[1];
    }
    __syncthreads();

    int wm = (warp >> 2) * 64, wn = (warp & 3) * 32;
    int a_r = (lane & 7) + ((lane & 16) ? 8 : 0);
    int a_c = (lane & 8) ? 8 : 0;
    int b_r = (lane & 7) + ((lane & 8) ? 8 : 0);
    int b_c = (lane & 16) ? 8 : 0;

    float acc[4][4][4] = {};
    for (int ch = 0; ch < 16; ch++) {
        int buf = ch & 1;
        uint4 pa0, pa1, pb0, pb1;
        if (ch < 15) {
            const uint4* as = (const uint4*)(Ag + ((ch + 1) * 32 + lrow) * 1024 + m0 + lcol);
            const uint4* bs = (const uint4*)(Bg + ((ch + 1) * 32 + lrow) * 1024 + n0 + lcol);
            pa0 = as[0]; pa1 = as[1];
            pb0 = bs[0]; pb1 = bs[1];
        }
#pragma unroll
        for (int ks = 0; ks < 2; ks++) {
            int kk = ks * 16;
            uint32_t af[4][4], bf[2][4];
#pragma unroll
            for (int mi = 0; mi < 4; mi++)
                ldm4t(af[mi], cvta_s(Asb[buf] + (kk + a_r) * 136 + wm + mi * 16 + a_c));
#pragma unroll
            for (int np = 0; np < 2; np++)
                ldm4t(bf[np], cvta_s(Bsb[buf] + (kk + b_r) * 136 + wn + np * 16 + b_c));
#pragma unroll
            for (int mi = 0; mi < 4; mi++)
#pragma unroll
                for (int ni = 0; ni < 4; ni++)
                    mma16816(acc[mi][ni], af[mi], &bf[ni >> 1][(ni & 1) * 2]);
        }
        if (ch < 15) {
            int nb = buf ^ 1;
            uint4* ad = (uint4*)(Asb[nb] + lrow * 136 + lcol);
            uint4* bd = (uint4*)(Bsb[nb] + lrow * 136 + lcol);
            ad[0] = pa0; ad[1] = pa1;
            bd[0] = pb0; bd[1] = pb1;
        }
        __syncthreads();
    }

    __half* stage = s1;
    int row = lane >> 2, colp = (lane & 3) * 2;
#pragma unroll
    for (int mi = 0; mi < 4; mi++)
#pragma unroll
        for (int ni = 0; ni < 4; ni++) {
            int rr = wm + mi * 16 + row, cc = wn + ni * 8 + colp;
            *(__half2*)&stage[rr * 136 + cc] =
                __floats2half2_rn(acc[mi][ni][0], acc[mi][ni][1]);
            *(__half2*)&stage[(rr + 8) * 136 + cc] =
                __floats2half2_rn(acc[mi][ni][2], acc[mi][ni][3]);
        }
    __syncthreads();

    __half* base = (w == 0) ? g_Qh : ((w == 1) ? g_Kh : g_Vh);
#pragma unroll
    for (int i = 0; i < 8; i++) {
        int idx = i * 256 + t;
        int rr = idx >> 4, chunk = idx & 15;
        int jp = n0 + chunk * 8;
        int h = jp >> 6, d = jp & 63;
        *(uint4*)(base + (((b * 16 + h) * 1024 + m0 + rr) << 6) + d) =
            *(const uint4*)&stage[rr * 136 + chunk * 8];
    }
}

// ================= K2: J = Q.K^T per (b,h), HMMA, staged epilogue, fp8 J out =======
__global__ __launch_bounds__(256) void k2_J() {
    __shared__ __half s2[18432];
    __half* As = s2;
    __half* Bs = s2 + 9216;
    int bh = blockIdx.z;
    int q0 = blockIdx.y * 128, k0 = blockIdx.x * 128;
    const __half* Qb = g_Qh + ((size_t)bh << 16);
    const __half* Kb = g_Kh + ((size_t)bh << 16);

    int t = threadIdx.x, lane = t & 31, warp = t >> 5;
    {
        int lr = t >> 1, ls = (t & 1) * 32;
        const uint4* qs = (const uint4*)(Qb + ((q0 + lr) << 6) + ls);
        const uint4* ks = (const uint4*)(Kb + ((k0 + lr) << 6) + ls);
        uint4* ad = (uint4*)(As + lr * 72 + ls);
        uint4* bd = (uint4*)(Bs + lr * 72 + ls);
#pragma unroll
        for (int i = 0; i < 4; i++) { ad[i] = qs[i]; bd[i] = ks[i]; }
    }
    __syncthreads();

    int wm = (warp >> 2) * 64, wn = (warp & 3) * 32;
    int amr = lane & 15, akc = (lane >> 4) * 8;
    int bnr = (lane & 7) + ((lane & 16) ? 8 : 0);
    int bkc = (lane & 8) ? 8 : 0;

    float acc[4][4][4] = {};
#pragma unroll
    for (int ks = 0; ks < 4; ks++) {
        int kk = ks * 16;
        uint32_t af[4][4], bf[2][4];
#pragma unroll
        for (int mi = 0; mi < 4; mi++)
            ldm4(af[mi], cvta_s(As + (wm + mi * 16 + amr) * 72 + kk + akc));
#pragma unroll
        for (int np = 0; np < 2; np++)
            ldm4(bf[np], cvta_s(Bs + (wn + np * 16 + bnr) * 72 + kk + bkc));
#pragma unroll
        for (int mi = 0; mi < 4; mi++)
#pragma unroll
            for (int ni = 0; ni < 4; ni++)
                mma16816(acc[mi][ni], af[mi], &bf[ni >> 1][(ni & 1) * 2]);
    }
    __syncthreads();

    __half* stage = s2;
    int row = lane >> 2, colp = (lane & 3) * 2;
#pragma unroll
    for (int mi = 0; mi < 4; mi++)
#pragma unroll
        for (int ni = 0; ni < 4; ni++) {
            int rr = wm + mi * 16 + row, cc = wn + ni * 8 + colp;
            *(__half2*)&stage[rr * 136 + cc] =
                __floats2half2_rn(acc[mi][ni][0], acc[mi][ni][1]);
            *(__half2*)&stage[(rr + 8) * 136 + cc] =
                __floats2half2_rn(acc[mi][ni][2], acc[mi][ni][3]);
        }
    __syncthreads();

    uint8_t* Jp = g_J + ((size_t)bh << 20);
#pragma unroll
    for (int i = 0; i < 4; i++) {
        int idx = i * 256 + t;                 // 0..1023
        int rr = idx >> 3, chunk = idx & 7;    // chunk of 16 fp8
        uint4 v = h16_to_f8x16((const uint32_t*)&stage[rr * 136 + chunk * 16]);
        *(uint4*)&Jp[(size_t)(q0 + rr) * 1024 + k0 + chunk * 16] = v;
    }
}

// ====== K34: EL = J@Wl - mask, softmax, U = W@Ww — 2 q's/block, pipelined J loads ==
// Block handles q and q+512. q1's fp8 J is issued into registers before q0's
// compute, hiding gmem latency behind the q0 MMA phases. exp stays in registers
// (phase-1 C-frag == phase-2 B-frag, thread-for-thread).
#define JST 1032
__global__ __launch_bounds__(256) void k34_softmax_U(const float* __restrict__ mask,
                                                     const float* __restrict__ Wl,
                                                     const float* __restrict__ Ww) {
    extern __shared__ __half sJd[];         // 2 x [16][JST] halves (66 KB)
    __shared__ __half sWl[16 * 24];
    __shared__ __half sWwS[16 * 24];
    __shared__ float sMask[1024];
    __shared__ float red[8][16];
    __shared__ float sInv[16];

    int qb = blockIdx.x, b = blockIdx.y;    // qb in [0,512)
    int tid = threadIdx.x, lane = tid & 31, w = tid >> 5;
    const uint8_t* JbB = g_J + (size_t)b * 16777216;

    { int h = tid >> 4, g = tid & 15; sWl[h * 24 + g] = __float2half(Wl[h * 16 + g]); }
    { float4 m4 = *(const float4*)(mask + b * 1024 + tid * 4);
      *(float4*)&sMask[tid * 4] = m4; }
    // load q0's J -> sJ0
    {
        const uint8_t* Jb0 = JbB + (size_t)qb * 1024;
#pragma unroll
        for (int p = 0; p < 2; p++) {
            int h = w * 2 + p;
            const uint4* src = (const uint4*)(Jb0 + (size_t)h * 1048576);
#pragma unroll
            for (int it = 0; it < 2; it++) {
                int c16 = lane + it * 32;
                uint4 hv[2];
                f8x16_to_h16(src[c16], hv);
                *(uint4*)&sJd[h * JST + c16 * 16]     = hv[0];
                *(uint4*)&sJd[h * JST + c16 * 16 + 8] = hv[1];
            }
        }
    }
    __syncthreads();

    // issue q1's raw fp8 J loads into registers (consumed after q0's compute)
    uint4 praw[4];
    {
        const uint8_t* Jb1 = JbB + (size_t)(qb + 512) * 1024;
#pragma unroll
        for (int p = 0; p < 2; p++) {
            const uint4* src = (const uint4*)(Jb1 + (size_t)(w * 2 + p) * 1048576);
            praw[p * 2]     = src[lane];
            praw[p * 2 + 1] = src[lane + 32];
        }
    }

    // common fragment constants
    uint32_t bWl[4];
    {
        int b_r = (lane & 7) + ((lane & 8) ? 8 : 0);
        int b_c = (lane & 16) ? 8 : 0;
        ldm4t(bWl, cvta_s(sWl + b_r * 24 + b_c));
    }
    int a_r = (lane & 7) + ((lane & 16) ? 8 : 0);
    int a_c = (lane & 8) ? 8 : 0;
    int r = lane >> 2, cg = (lane & 3) * 2;
    int kbase = w * 128;

    for (int qq = 0; qq < 2; qq++) {
        __half* sJ = sJd + qq * 16 * JST;
        int q = qb + qq * 512;
        if (qq == 1) {
            // convert q1's raw J into sJ1
#pragma unroll
            for (int p = 0; p < 2; p++) {
                int h = w * 2 + p;
#pragma unroll
                for (int it = 0; it < 2; it++) {
                    int c16 = lane + it * 32;
                    uint4 hv[2];
                    f8x16_to_h16(praw[p * 2 + it], hv);
                    *(uint4*)&sJ[h * JST + c16 * 16]     = hv[0];
                    *(uint4*)&sJ[h * JST + c16 * 16 + 8] = hv[1];
                }
            }
            __syncthreads();
        }

        // ---- phase 1: EL tiles + exp; e stays in registers ----
        float psum4[4] = {};
        uint32_t eh[8][4];
#pragma unroll
        for (int i = 0; i < 8; i++) {
            int kcol = kbase + i * 16;
            uint32_t af[4];
            ldm4t(af, cvta_s(sJ + a_r * JST + kcol + a_c));
            float c0[4] = {}, c1[4] = {};
            mma16816(c0, af, &bWl[0]);   // g 0-7
            mma16816(c1, af, &bWl[2]);   // g 8-15
            float mk0 = sMask[kcol + r], mk1 = sMask[kcol + r + 8];
            float e00 = fast_exp(c0[0] - mk0), e01 = fast_exp(c0[1] - mk0);
            float e02 = fast_exp(c0[2] - mk1), e03 = fast_exp(c0[3] - mk1);
            float e10 = fast_exp(c1[0] - mk0), e11 = fast_exp(c1[1] - mk0);
            float e12 = fast_exp(c1[2] - mk1), e13 = fast_exp(c1[3] - mk1);
            psum4[0] += e00 + e02; psum4[1] += e01 + e03;
            psum4[2] += e10 + e12; psum4[3] += e11 + e13;
            eh[i][0] = h2u(__floats2half2_rn(e00, e01));
            eh[i][1] = h2u(__floats2half2_rn(e10, e11));
            eh[i][2] = h2u(__floats2half2_rn(e02, e03));
            eh[i][3] = h2u(__floats2half2_rn(e12, e13));
        }
#pragma unroll
        for (int s = 16; s >= 4; s >>= 1) {
#pragma unroll
            for (int j = 0; j < 4; j++)
                psum4[j] += __shfl_xor_sync(0xffffffffu, psum4[j], s);
        }
        if (lane < 4) {
            red[w][2 * lane]     = psum4[0];
            red[w][2 * lane + 1] = psum4[1];
            red[w][2 * lane + 8] = psum4[2];
            red[w][2 * lane + 9] = psum4[3];
        }
        __syncthreads();
        if (tid < 16) {
            float s = 0.f;
#pragma unroll
            for (int ww = 0; ww < 8; ww++) s += red[ww][tid];
            sInv[tid] = USCALE / s;
        }
        __syncthreads();
        { int v = tid >> 4, g = tid & 15;
          sWwS[v * 24 + g] = __float2half(sInv[g] * Ww[g * 16 + v]); }
        __syncthreads();

        // ---- phase 2: U^T from register B-frags; stage fp16, fp8 bulk store ----
        uint32_t aW[4];
        { int amr = lane & 15, akc2 = (lane >> 4) * 8;
          ldm4(aW, cvta_s(sWwS + amr * 24 + akc2)); }
#pragma unroll
        for (int i = 0; i < 8; i++) {
            int kcol = kbase + i * 16;
            float c0[4] = {}, c1[4] = {};
            mma16816(c0, aW, &eh[i][0]);   // kpos 0-7
            mma16816(c1, aW, &eh[i][2]);   // kpos 8-15
            *(__half2*)&sJ[r * JST + kcol + cg]           = __floats2half2_rn(c0[0], c0[1]);
            *(__half2*)&sJ[(r + 8) * JST + kcol + cg]     = __floats2half2_rn(c0[2], c0[3]);
            *(__half2*)&sJ[r * JST + kcol + 8 + cg]       = __floats2half2_rn(c1[0], c1[1]);
            *(__half2*)&sJ[(r + 8) * JST + kcol + 8 + cg] = __floats2half2_rn(c1[2], c1[3]);
        }
        __syncwarp();
        uint8_t* Ub = g_U + (size_t)b * 16777216 + (size_t)q * 1024;
#pragma unroll
        for (int it = 0; it < 4; it++) {
            int idx = lane + it * 32;          // 0..127 : 16 v-rows x 8 chunks(16 fp8)
            int v = idx >> 3, uu = (idx & 7) * 16;
            uint4 o = h16_to_f8x16((const uint32_t*)&sJ[v * JST + kbase + uu]);
            *(uint4*)&Ub[(size_t)v * 1048576 + kbase + uu] = o;
        }
    }
}

// ================= K5: O = U.V per (b,v), HMMA, 128x64, KC=64 DB, fp8 U in =========
__global__ __launch_bounds__(256) void k5_O() {
    extern __shared__ __half sm5[];
    __half* Asb[2] = { sm5, sm5 + 128 * 72 };
    __half* Bsb[2] = { sm5 + 2 * 128 * 72, sm5 + 2 * 128 * 72 + 64 * 72 };
    int bv = blockIdx.y;
    int b = bv >> 4, v = bv & 15;
    int q0 = blockIdx.x * 128;
    const uint8_t* U = g_U + ((size_t)bv << 20);
    const __half* Vb = g_Vh + ((size_t)bv << 16);

    int t = threadIdx.x, lane = t & 31, warp = t >> 5;
    int alr = t >> 1, als = (t & 1) * 32;
    int blr = t >> 2, bls = (t & 3) * 16;

    {
        const uint4* as = (const uint4*)(U + (size_t)(q0 + alr) * 1024 + als);
        uint4* ad = (uint4*)(Asb[0] + alr * 72 + als);
        uint4 cv[2];
        f8x16_to_h16(as[0], cv); ad[0] = cv[0]; ad[1] = cv[1];
        f8x16_to_h16(as[1], cv); ad[2] = cv[0]; ad[3] = cv[1];
        const uint4* bs = (const uint4*)(Vb + (blr << 6) + bls);
        uint4* bd = (uint4*)(Bsb[0] + blr * 72 + bls);
        bd[0] = bs[0]; bd[1] = bs[1];
    }
    __syncthreads();

    int wm = (warp >> 1) * 32, wn = (warp & 1) * 32;
    int amr = lane & 15, akc = (lane >> 4) * 8;
    int btr = (lane & 7) + ((lane & 8) ? 8 : 0);
    int btc = (lane & 16) ? 8 : 0;

    float acc[2][4][4] = {};
    for (int ch = 0; ch < 16; ch++) {
        int buf = ch & 1;
        uint4 pa[2], pb[2];
        if (ch < 15) {
            int kn = (ch + 1) * 64;
            const uint4* as = (const uint4*)(U + (size_t)(q0 + alr) * 1024 + kn + als);
            pa[0] = as[0]; pa[1] = as[1];
            const uint4* bs = (const uint4*)(Vb + ((kn + blr) << 6) + bls);
            pb[0] = bs[0]; pb[1] = bs[1];
        }
#pragma unroll
        for (int ks = 0; ks < 4; ks++) {
            int kk = ks * 16;
            uint32_t af[2][4], bf[2][4];
#pragma unroll
            for (int mi = 0; mi < 2; mi++)
                ldm4(af[mi], cvta_s(Asb[buf] + (wm + mi * 16 + amr) * 72 + kk + akc));
#pragma unroll
            for (int np = 0; np < 2; np++)
                ldm4t(bf[np], cvta_s(Bsb[buf] + (kk + btr) * 72 + wn + np * 16 + btc));
#pragma unroll
            for (int mi = 0; mi < 2; mi++)
#pragma unroll
                for (int ni = 0; ni < 4; ni++)
                    mma16816(acc[mi][ni], af[mi], &bf[ni >> 1][(ni & 1) * 2]);
        }
        if (ch < 15) {
            int nb = buf ^ 1;
            uint4* ad = (uint4*)(Asb[nb] + alr * 72 + als);
            uint4 cv[2];
            f8x16_to_h16(pa[0], cv); ad[0] = cv[0]; ad[1] = cv[1];
            f8x16_to_h16(pa[1], cv); ad[2] = cv[0]; ad[3] = cv[1];
            uint4* bd = (uint4*)(Bsb[nb] + blr * 72 + bls);
            bd[0] = pb[0]; bd[1] = pb[1];
        }
        __syncthreads();
    }

    int row = lane >> 2, colp = (lane & 3) * 2;
#pragma unroll
    for (int mi = 0; mi < 2; mi++) {
        int q = q0 + wm + mi * 16 + row;
#pragma unroll
        for (int ni = 0; ni < 4; ni++) {
            int d = wn + ni * 8 + colp;
            __half* p = g_Oh + b * 1048576 + q * 1024 + v * 64 + d;
            *(__half2*)p = __floats2half2_rn(acc[mi][ni][0] * UINV, acc[mi][ni][1] * UINV);
            *(__half2*)(p + 8 * 1024) =
                __floats2half2_rn(acc[mi][ni][2] * UINV, acc[mi][ni][3] * UINV);
        }
    }
}

// ================= K6: out[b,c,q] = inp + O @ Wo16, HMMA 64q x 64c, KC=64 DB =======
__global__ __launch_bounds__(256) void k6_out(const float* __restrict__ inp,
                                              float* __restrict__ out) {
    extern __shared__ __half sm6[];
    __half* Asb[2] = { sm6, sm6 + 64 * 72 };
    __half* Bsb[2] = { sm6 + 2 * 64 * 72, sm6 + 2 * 64 * 72 + 64 * 72 };
    float* Cs = (float*)sm6;
    int b = blockIdx.z;
    int c0 = blockIdx.x * 64, q0 = blockIdx.y * 64;
    const __half* Oq = g_Oh + b * 1048576;

    int t = threadIdx.x, lane = t & 31, w = t >> 5;
    int lr = t >> 2, ls = (t & 3) * 16;

    {
        const uint4* as = (const uint4*)(Oq + (q0 + lr) * 1024 + ls);
        uint4* ad = (uint4*)(Asb[0] + lr * 72 + ls);
        ad[0] = as[0]; ad[1] = as[1];
        const uint4* bs = (const uint4*)(g_Wo16 + lr * 512 + c0 + ls);
        uint4* bd = (uint4*)(Bsb[0] + lr * 72 + ls);
        bd[0] = bs[0]; bd[1] = bs[1];
    }
    __syncthreads();

    int wm = (w >> 2) * 32, wn = (w & 3) * 16;
    int amr = lane & 15, akc = (lane >> 4) * 8;
    int b_r = (lane & 7) + ((lane & 8) ? 8 : 0);
    int b_c = (lane & 16) ? 8 : 0;

    float acc[2][2][4] = {};
    for (int ch = 0; ch < 16; ch++) {
        int buf = ch & 1;
        uint4 pa[2], pb[2];
        if (ch < 15) {
            int kn = (ch + 1) * 64;
            const uint4* as = (const uint4*)(Oq + (q0 + lr) * 1024 + kn + ls);
            pa[0] = as[0]; pa[1] = as[1];
            const uint4* bs = (const uint4*)(g_Wo16 + (kn + lr) * 512 + c0 + ls);
            pb[0] = bs[0]; pb[1] = bs[1];
        }
#pragma unroll
        for (int ks = 0; ks < 4; ks++) {
            int kk = ks * 16;
            uint32_t af[2][4], bf[4];
#pragma unroll
            for (int mi = 0; mi < 2; mi++)
                ldm4(af[mi], cvta_s(Asb[buf] + (wm + mi * 16 + amr) * 72 + kk + akc));
            ldm4t(bf, cvta_s(Bsb[buf] + (kk + b_r) * 72 + wn + b_c));
#pragma unroll
            for (int mi = 0; mi < 2; mi++)
#pragma unroll
                for (int ni = 0; ni < 2; ni++)
                    mma16816(acc[mi][ni], af[mi], &bf[ni * 2]);
        }
        if (ch < 15) {
            int nb = buf ^ 1;
            uint4* ad = (uint4*)(Asb[nb] + lr * 72 + ls);
            ad[0] = pa[0]; ad[1] = pa[1];
            uint4* bd = (uint4*)(Bsb[nb] + lr * 72 + ls);
            bd[0] = pb[0]; bd[1] = pb[1];
        }
        __syncthreads();
    }

    int row = lane >> 2, cp = (lane & 3) * 2;
#pragma unroll
    for (int mi = 0; mi < 2; mi++)
#pragma unroll
        for (int ni = 0; ni < 2; ni++) {
            int qq = wm + mi * 16 + row;
            int cc2 = wn + ni * 8 + cp;
            Cs[cc2 * 68 + qq]           = acc[mi][ni][0];
            Cs[(cc2 + 1) * 68 + qq]     = acc[mi][ni][1];
            Cs[cc2 * 68 + qq + 8]       = acc[mi][ni][2];
            Cs[(cc2 + 1) * 68 + qq + 8] = acc[mi][ni][3];
        }
    __syncthreads();
#pragma unroll
    for (int i2 = 0; i2 < 4; i2++) {
        int idx = t + i2 * 256;
        int cc2 = idx >> 4, q4 = (idx & 15) * 4;
        size_t off = (size_t)b * 524288 + (size_t)(c0 + cc2) * 1024 + q0 + q4;
        float4 iv = *(const float4*)(inp + off);
        *(float4*)(out + off) = make_float4(iv.x + Cs[cc2 * 68 + q4],
                                            iv.y + Cs[cc2 * 68 + q4 + 1],
                                            iv.z + Cs[cc2 * 68 + q4 + 2],
                                            iv.w + Cs[cc2 * 68 + q4 + 3]);
    }
}

// ================= launch =================
extern "C" void kernel_launch(void* const* d_in, const int* in_sizes, int n_in,
                              void* d_out, int out_size) {
    const float* inp  = (const float*)d_in[0];
    const float* mask = (const float*)d_in[1];
    const float* Wq   = (const float*)d_in[2];
    const float* Wk   = (const float*)d_in[3];
    const float* Wv   = (const float*)d_in[4];
    const float* aq   = (const float*)d_in[5];
    const float* ak   = (const float*)d_in[6];
    const float* av   = (const float*)d_in[7];
    const float* Wl   = (const float*)d_in[8];
    const float* Ww   = (const float*)d_in[9];
    const float* Wo   = (const float*)d_in[10];
    float* out = (float*)d_out;

    const int SMEM_K34 = 2 * 16 * JST * 2;                    // 66048
    const int SMEM_K5  = (2 * 128 * 72 + 2 * 64 * 72) * 2;    // 55296
    const int SMEM_K6  = 4 * 64 * 72 * 2;                     // 36864
    cudaFuncSetAttribute(k34_softmax_U, cudaFuncAttributeMaxDynamicSharedMemorySize, SMEM_K34);
    cudaFuncSetAttribute(k5_O, cudaFuncAttributeMaxDynamicSharedMemorySize, SMEM_K5);
    cudaFuncSetAttribute(k6_out, cudaFuncAttributeMaxDynamicSharedMemorySize, SMEM_K6);

    kc0<<<3264, 256>>>(inp, Wq, Wk, Wv, aq, ak, av, Wo);
    k1_proj<<<dim3(8, 8, 6), 256>>>();
    k2_J<<<dim3(8, 8, 32), 256>>>();
    k34_softmax_U<<<dim3(512, 2), 256, SMEM_K34>>>(mask, Wl, Ww);
    k5_O<<<dim3(8, 32), 256, SMEM_K5>>>();
    k6_out<<<dim3(8, 16, 2), 256, SMEM_K6>>>(inp, out);
}